// round 4
// baseline (speedup 1.0000x reference)
#include <cuda_runtime.h>
#include <cstddef>

// Problem constants (match reference setup_inputs)
#define NN 100000
#define DD 128
#define EE_MAX 600000
#define LL_MAX 200000

// Scratch (allocation-free rule: __device__ globals)
__device__ float g_agg[(size_t)NN * DD];   // 51.2 MB
__device__ float g_x1 [(size_t)NN * DD];   // 51.2 MB
__device__ float g_x2 [(size_t)NN * DD];   // 51.2 MB
__device__ float g_inv[NN];
__device__ int   g_cnt[NN];

// ---------------------------------------------------------------------------
// Degree count + inverse
// ---------------------------------------------------------------------------
__global__ void deg_kernel(const int* __restrict__ dst, int e) {
    int i = blockIdx.x * blockDim.x + threadIdx.x;
    if (i < e) atomicAdd(&g_cnt[dst[i]], 1);
}

__global__ void inv_kernel(int n) {
    int i = blockIdx.x * blockDim.x + threadIdx.x;
    if (i < n) g_inv[i] = 1.0f / fmaxf((float)g_cnt[i], 1.0f);
}

// ---------------------------------------------------------------------------
// Scatter: g_agg[dst] += x[src]   (one warp per edge, float4 vector atomics)
// ---------------------------------------------------------------------------
__global__ void scatter_kernel(const float* __restrict__ x,
                               const int* __restrict__ src,
                               const int* __restrict__ dst, int e) {
    int w    = (blockIdx.x * blockDim.x + threadIdx.x) >> 5;
    int lane = threadIdx.x & 31;
    if (w >= e) return;
    int s = __ldg(src + w);
    int d = __ldg(dst + w);
    float4 v = *(const float4*)(x + (size_t)s * DD + lane * 4);
    // sm_90+ vector reduction: lowers to RED.E.ADD.F32 (v4), no return value
    atomicAdd((float4*)(g_agg + (size_t)d * DD + lane * 4), v);
}

// ---------------------------------------------------------------------------
// Fused SAGE layer GEMM: out = act( (agg * inv_deg) @ Wl + b + xin @ Wr )
// Persistent blocks, Wl/Wr resident in shared (128 KB), 64-row tiles,
// 4 rows x 4 cols per thread (512 threads).
// ---------------------------------------------------------------------------
#define TILE_ROWS 64
#define GEMM_THREADS 512
// floats: Wl 16384 + Wr 16384 + A 8192 + X 8192 + b 128
#define GEMM_SMEM_FLOATS (16384 + 16384 + 8192 + 8192 + 128)
#define GEMM_SMEM_BYTES  (GEMM_SMEM_FLOATS * 4)

__global__ __launch_bounds__(GEMM_THREADS, 1)
void sage_gemm_kernel(const float* __restrict__ agg,
                      const float* __restrict__ xin,
                      const float* __restrict__ Wl,
                      const float* __restrict__ bias,
                      const float* __restrict__ Wr,
                      float* __restrict__ out,
                      int n, int do_relu) {
    extern __shared__ float sm[];
    float* Wls = sm;                 // [128][128]
    float* Wrs = Wls + 16384;        // [128][128]
    float* As  = Wrs + 16384;        // [64][128]
    float* Xs  = As + TILE_ROWS * DD;
    float* bs  = Xs + TILE_ROWS * DD;

    int tid = threadIdx.x;

    // Load weights into shared once per block (persistent blocks)
    for (int i = tid; i < 4096; i += GEMM_THREADS) {
        ((float4*)Wls)[i] = ((const float4*)Wl)[i];
        ((float4*)Wrs)[i] = ((const float4*)Wr)[i];
    }
    if (tid < DD) bs[tid] = bias[tid];
    __syncthreads();

    int rg  = tid >> 5;      // 0..15  (warp index -> row group)
    int cg  = tid & 31;      // 0..31  (lane -> column group of 4)
    int r0  = rg * 4;
    int cg4 = cg * 4;

    int ntiles = (n + TILE_ROWS - 1) / TILE_ROWS;
    for (int t = blockIdx.x; t < ntiles; t += gridDim.x) {
        int base = t * TILE_ROWS;

        // Load A (scaled by inv degree -> mean) and X tiles
        for (int i = tid; i < TILE_ROWS * 32; i += GEMM_THREADS) {
            int row = i >> 5, c4 = i & 31;
            int gr = base + row;
            if (gr < n) {
                float inv = g_inv[gr];
                float4 a = ((const float4*)(agg + (size_t)gr * DD))[c4];
                a.x *= inv; a.y *= inv; a.z *= inv; a.w *= inv;
                ((float4*)(As + row * DD))[c4] = a;
                ((float4*)(Xs + row * DD))[c4] =
                    ((const float4*)(xin + (size_t)gr * DD))[c4];
            }
        }
        __syncthreads();

        float4 acc[4];
        float4 bv = *(float4*)(bs + cg4);
        acc[0] = bv; acc[1] = bv; acc[2] = bv; acc[3] = bv;

        #pragma unroll 8
        for (int k = 0; k < DD; k++) {
            float4 wl = *(float4*)(Wls + k * DD + cg4);
            float4 wr = *(float4*)(Wrs + k * DD + cg4);
            #pragma unroll
            for (int r = 0; r < 4; r++) {
                float a = As[(r0 + r) * DD + k];   // warp-broadcast
                float x = Xs[(r0 + r) * DD + k];   // warp-broadcast
                acc[r].x = fmaf(a, wl.x, fmaf(x, wr.x, acc[r].x));
                acc[r].y = fmaf(a, wl.y, fmaf(x, wr.y, acc[r].y));
                acc[r].z = fmaf(a, wl.z, fmaf(x, wr.z, acc[r].z));
                acc[r].w = fmaf(a, wl.w, fmaf(x, wr.w, acc[r].w));
            }
        }

        #pragma unroll
        for (int r = 0; r < 4; r++) {
            int gr = base + r0 + r;
            if (gr < n) {
                float4 v = acc[r];
                if (do_relu) {
                    v.x = fmaxf(v.x, 0.f); v.y = fmaxf(v.y, 0.f);
                    v.z = fmaxf(v.z, 0.f); v.w = fmaxf(v.w, 0.f);
                }
                *(float4*)(out + (size_t)gr * DD + cg4) = v;
            }
        }
        __syncthreads();
    }
}

// ---------------------------------------------------------------------------
// Link predictor: out[l] = dot(x2[s], Wlin[0:128]) + dot(x2[d], Wlin[128:256]) + blin
// One warp per label.
// ---------------------------------------------------------------------------
__global__ void predict_kernel(const int* __restrict__ s,
                               const int* __restrict__ d,
                               const float* __restrict__ Wlin,
                               const float* __restrict__ blin,
                               float* __restrict__ out, int L) {
    int w    = (blockIdx.x * blockDim.x + threadIdx.x) >> 5;
    int lane = threadIdx.x & 31;
    if (w >= L) return;
    int si = __ldg(s + w);
    int di = __ldg(d + w);
    float4 a  = *(const float4*)(g_x2 + (size_t)si * DD + lane * 4);
    float4 b  = *(const float4*)(g_x2 + (size_t)di * DD + lane * 4);
    float4 w0 = *(const float4*)(Wlin + lane * 4);
    float4 w1 = *(const float4*)(Wlin + DD + lane * 4);
    float acc = a.x * w0.x + a.y * w0.y + a.z * w0.z + a.w * w0.w
              + b.x * w1.x + b.y * w1.y + b.z * w1.z + b.w * w1.w;
    #pragma unroll
    for (int o = 16; o > 0; o >>= 1)
        acc += __shfl_down_sync(0xFFFFFFFFu, acc, o);
    if (lane == 0) out[w] = acc + __ldg(blin);
}

// ---------------------------------------------------------------------------
// Launch
// ---------------------------------------------------------------------------
extern "C" void kernel_launch(void* const* d_in, const int* in_sizes, int n_in,
                              void* d_out, int out_size) {
    const int*   ei   = (const int*)d_in[0];     // [2, E]
    const int*   eli  = (const int*)d_in[1];     // [2, L]
    const float* emb  = (const float*)d_in[2];   // [N, 128]
    const float* W1l  = (const float*)d_in[3];
    const float* b1   = (const float*)d_in[4];
    const float* W1r  = (const float*)d_in[5];
    const float* W2l  = (const float*)d_in[6];
    const float* b2   = (const float*)d_in[7];
    const float* W2r  = (const float*)d_in[8];
    const float* Wlin = (const float*)d_in[9];
    const float* blin = (const float*)d_in[10];
    float*       out  = (float*)d_out;

    const int E = in_sizes[0] / 2;
    const int L = in_sizes[1] / 2;
    const int N = in_sizes[2] / DD;

    const int* src = ei;
    const int* dst = ei + E;
    const int* ls  = eli;
    const int* ld  = eli + L;

    void* p_agg = nullptr; cudaGetSymbolAddress(&p_agg, g_agg);
    void* p_cnt = nullptr; cudaGetSymbolAddress(&p_cnt, g_cnt);

    cudaFuncSetAttribute(sage_gemm_kernel,
                         cudaFuncAttributeMaxDynamicSharedMemorySize,
                         GEMM_SMEM_BYTES);

    float* x1 = nullptr; cudaGetSymbolAddress((void**)&x1, g_x1);
    float* agg = (float*)p_agg;
    float* x2 = nullptr; cudaGetSymbolAddress((void**)&x2, g_x2);

    const int scatter_blocks = ((size_t)E * 32 + 255) / 256;
    const int gemm_grid = 148;

    // Degrees (once) + zero accumulator
    cudaMemsetAsync(p_cnt, 0, sizeof(int) * (size_t)N);
    cudaMemsetAsync(p_agg, 0, sizeof(float) * (size_t)N * DD);
    deg_kernel<<<(E + 255) / 256, 256>>>(dst, E);
    inv_kernel<<<(N + 255) / 256, 256>>>(N);

    // Layer 1
    scatter_kernel<<<scatter_blocks, 256>>>(emb, src, dst, E);
    sage_gemm_kernel<<<gemm_grid, GEMM_THREADS, GEMM_SMEM_BYTES>>>(
        agg, emb, W1l, b1, W1r, x1, N, /*relu=*/1);

    // Layer 2
    cudaMemsetAsync(p_agg, 0, sizeof(float) * (size_t)N * DD);
    scatter_kernel<<<scatter_blocks, 256>>>(x1, src, dst, E);
    sage_gemm_kernel<<<gemm_grid, GEMM_THREADS, GEMM_SMEM_BYTES>>>(
        agg, x1, W2l, b2, W2r, x2, N, /*relu=*/0);

    // Link prediction
    predict_kernel<<<((size_t)L * 32 + 127) / 128, 128>>>(ls, ld, Wlin, blin, out, L);
}

// round 5
// speedup vs baseline: 1.0171x; 1.0171x over previous
#include <cuda_runtime.h>
#include <cstddef>

#define NN 100000
#define DD 128
#define EE_MAX 600000
#define LL_MAX 200000

__device__ float g_agg[(size_t)NN * DD];
__device__ float g_x1 [(size_t)NN * DD];
__device__ float g_x2 [(size_t)NN * DD];
__device__ float g_inv[NN];
__device__ int   g_cnt[NN];

// ---------------------------------------------------------------------------
__global__ void deg_kernel(const int* __restrict__ dst, int e) {
    int i = blockIdx.x * blockDim.x + threadIdx.x;
    if (i < e) atomicAdd(&g_cnt[dst[i]], 1);
}

__global__ void inv_kernel(int n) {
    int i = blockIdx.x * blockDim.x + threadIdx.x;
    if (i < n) g_inv[i] = 1.0f / fmaxf((float)g_cnt[i], 1.0f);
}

// ---------------------------------------------------------------------------
__global__ void scatter_kernel(const float* __restrict__ x,
                               const int* __restrict__ src,
                               const int* __restrict__ dst, int e) {
    int w    = (blockIdx.x * blockDim.x + threadIdx.x) >> 5;
    int lane = threadIdx.x & 31;
    if (w >= e) return;
    int s = __ldg(src + w);
    int d = __ldg(dst + w);
    float4 v = *(const float4*)(x + (size_t)s * DD + lane * 4);
    atomicAdd((float4*)(g_agg + (size_t)d * DD + lane * 4), v);
}

// ---------------------------------------------------------------------------
// Packed dual-GEMM SAGE layer:
//   out = act( (agg*inv) @ Wl + b + xin @ Wr )
// f32x2 trick: operand pair (a, x), weight pair (Wl, Wr) -> one fma.rn.f32x2
// does both GEMMs; fold lo+hi at the end.
// ---------------------------------------------------------------------------
#define TILE_ROWS 64
#define GEMM_THREADS 512
// floats: Wi interleaved 128*128*2 = 32768, AXs 64*128*2 = 16384, bias 128
#define GEMM_SMEM_FLOATS (32768 + 16384 + 128)
#define GEMM_SMEM_BYTES  (GEMM_SMEM_FLOATS * 4)

typedef unsigned long long ull;

__device__ __forceinline__ void ffma2(ull& d, ull a, ull b) {
    asm volatile("fma.rn.f32x2 %0, %1, %2, %0;" : "+l"(d) : "l"(a), "l"(b));
}

__global__ __launch_bounds__(GEMM_THREADS, 1)
void sage_gemm_kernel(const float* __restrict__ agg,
                      const float* __restrict__ xin,
                      const float* __restrict__ Wl,
                      const float* __restrict__ bias,
                      const float* __restrict__ Wr,
                      float* __restrict__ out,
                      int n, int do_relu) {
    extern __shared__ float sm[];
    float* Wi  = sm;                       // [128][128] float2 pairs (wl,wr)
    float* AXs = Wi + 32768;               // [64][128] float2 pairs (a,x)
    float* bs  = AXs + TILE_ROWS * DD * 2; // [128]

    const int tid = threadIdx.x;

    // Build interleaved weights once per (persistent) block.
    // idx4 covers 4096 float4 positions of Wl/Wr.
    for (int i = tid; i < 4096; i += GEMM_THREADS) {
        float4 l = ((const float4*)Wl)[i];
        float4 r = ((const float4*)Wr)[i];
        float4 o0 = make_float4(l.x, r.x, l.y, r.y);
        float4 o1 = make_float4(l.z, r.z, l.w, r.w);
        ((float4*)Wi)[i * 2 + 0] = o0;
        ((float4*)Wi)[i * 2 + 1] = o1;
    }
    if (tid < DD) bs[tid] = bias[tid];
    __syncthreads();

    const int lane = tid & 31;   // base column
    const int rg   = tid >> 5;   // warp -> row group of 4
    const int r0   = rg * 4;

    const int ntiles = (n + TILE_ROWS - 1) / TILE_ROWS;
    for (int t = blockIdx.x; t < ntiles; t += gridDim.x) {
        const int base = t * TILE_ROWS;

        // Stage interleaved (a, x) pairs: AXs[row][k] = (agg[row][k]*inv, x[row][k])
        for (int i = tid; i < TILE_ROWS * 32; i += GEMM_THREADS) {
            int row = i >> 5, c4 = i & 31;
            int gr = base + row;
            if (gr < n) {
                float inv = g_inv[gr];
                float4 a = ((const float4*)(agg + (size_t)gr * DD))[c4];
                float4 x = ((const float4*)(xin + (size_t)gr * DD))[c4];
                a.x *= inv; a.y *= inv; a.z *= inv; a.w *= inv;
                float4 o0 = make_float4(a.x, x.x, a.y, x.y);
                float4 o1 = make_float4(a.z, x.z, a.w, x.w);
                float4* dst4 = (float4*)(AXs + (row * DD + c4 * 4) * 2);
                dst4[0] = o0;
                dst4[1] = o1;
            }
        }
        __syncthreads();

        // acc[r][j]: row r0+r, col lane+32j, packed (accA, accX)
        ull acc[4][4];
        #pragma unroll
        for (int r = 0; r < 4; r++)
            #pragma unroll
            for (int j = 0; j < 4; j++) acc[r][j] = 0ull;

        const ull* Wiu  = (const ull*)Wi;    // [k*128 + c] -> (wl,wr)
        const ull* AXu  = (const ull*)AXs;   // [row*128 + k] -> (a,x)

        #pragma unroll 4
        for (int k = 0; k < DD; k += 2) {
            // weights for k, k+1 at cols lane + 32j (conflict-free LDS.64)
            ull w0[4], w1[4];
            #pragma unroll
            for (int j = 0; j < 4; j++) {
                w0[j] = Wiu[(k    ) * DD + lane + 32 * j];
                w1[j] = Wiu[(k + 1) * DD + lane + 32 * j];
            }
            #pragma unroll
            for (int r = 0; r < 4; r++) {
                // broadcast 16B: (a,x) for k and k+1 of this row
                ulonglong2 ax = *(const ulonglong2*)(AXu + (r0 + r) * DD + k);
                #pragma unroll
                for (int j = 0; j < 4; j++) {
                    ffma2(acc[r][j], ax.x, w0[j]);
                    ffma2(acc[r][j], ax.y, w1[j]);
                }
            }
        }

        // Epilogue: fold (accA + accX) + bias, optional relu, coalesced stores
        #pragma unroll
        for (int r = 0; r < 4; r++) {
            int gr = base + r0 + r;
            if (gr < n) {
                #pragma unroll
                for (int j = 0; j < 4; j++) {
                    int c = lane + 32 * j;
                    float2 v = *(float2*)&acc[r][j];
                    float s = v.x + v.y + bs[c];
                    if (do_relu) s = fmaxf(s, 0.f);
                    out[(size_t)gr * DD + c] = s;
                }
            }
        }
        __syncthreads();
    }
}

// ---------------------------------------------------------------------------
__global__ void predict_kernel(const int* __restrict__ s,
                               const int* __restrict__ d,
                               const float* __restrict__ Wlin,
                               const float* __restrict__ blin,
                               float* __restrict__ out, int L) {
    int w    = (blockIdx.x * blockDim.x + threadIdx.x) >> 5;
    int lane = threadIdx.x & 31;
    if (w >= L) return;
    int si = __ldg(s + w);
    int di = __ldg(d + w);
    float4 a  = *(const float4*)(g_x2 + (size_t)si * DD + lane * 4);
    float4 b  = *(const float4*)(g_x2 + (size_t)di * DD + lane * 4);
    float4 w0 = *(const float4*)(Wlin + lane * 4);
    float4 w1 = *(const float4*)(Wlin + DD + lane * 4);
    float acc = a.x * w0.x + a.y * w0.y + a.z * w0.z + a.w * w0.w
              + b.x * w1.x + b.y * w1.y + b.z * w1.z + b.w * w1.w;
    #pragma unroll
    for (int o = 16; o > 0; o >>= 1)
        acc += __shfl_down_sync(0xFFFFFFFFu, acc, o);
    if (lane == 0) out[w] = acc + __ldg(blin);
}

// ---------------------------------------------------------------------------
extern "C" void kernel_launch(void* const* d_in, const int* in_sizes, int n_in,
                              void* d_out, int out_size) {
    const int*   ei   = (const int*)d_in[0];
    const int*   eli  = (const int*)d_in[1];
    const float* emb  = (const float*)d_in[2];
    const float* W1l  = (const float*)d_in[3];
    const float* b1   = (const float*)d_in[4];
    const float* W1r  = (const float*)d_in[5];
    const float* W2l  = (const float*)d_in[6];
    const float* b2   = (const float*)d_in[7];
    const float* W2r  = (const float*)d_in[8];
    const float* Wlin = (const float*)d_in[9];
    const float* blin = (const float*)d_in[10];
    float*       out  = (float*)d_out;

    const int E = in_sizes[0] / 2;
    const int L = in_sizes[1] / 2;
    const int N = in_sizes[2] / DD;

    const int* src = ei;
    const int* dst = ei + E;
    const int* ls  = eli;
    const int* ld  = eli + L;

    void* p_agg = nullptr; cudaGetSymbolAddress(&p_agg, g_agg);
    void* p_cnt = nullptr; cudaGetSymbolAddress(&p_cnt, g_cnt);

    cudaFuncSetAttribute(sage_gemm_kernel,
                         cudaFuncAttributeMaxDynamicSharedMemorySize,
                         GEMM_SMEM_BYTES);

    float* x1 = nullptr; cudaGetSymbolAddress((void**)&x1, g_x1);
    float* agg = (float*)p_agg;
    float* x2 = nullptr; cudaGetSymbolAddress((void**)&x2, g_x2);

    const int scatter_blocks = ((size_t)E * 32 + 255) / 256;
    const int gemm_grid = 148;

    cudaMemsetAsync(p_cnt, 0, sizeof(int) * (size_t)N);
    cudaMemsetAsync(p_agg, 0, sizeof(float) * (size_t)N * DD);
    deg_kernel<<<(E + 255) / 256, 256>>>(dst, E);
    inv_kernel<<<(N + 255) / 256, 256>>>(N);

    scatter_kernel<<<scatter_blocks, 256>>>(emb, src, dst, E);
    sage_gemm_kernel<<<gemm_grid, GEMM_THREADS, GEMM_SMEM_BYTES>>>(
        agg, emb, W1l, b1, W1r, x1, N, 1);

    cudaMemsetAsync(p_agg, 0, sizeof(float) * (size_t)N * DD);
    scatter_kernel<<<scatter_blocks, 256>>>(x1, src, dst, E);
    sage_gemm_kernel<<<gemm_grid, GEMM_THREADS, GEMM_SMEM_BYTES>>>(
        agg, x1, W2l, b2, W2r, x2, N, 0);

    predict_kernel<<<((size_t)L * 32 + 127) / 128, 128>>>(ls, ld, Wlin, blin, out, L);
}